// round 7
// baseline (speedup 1.0000x reference)
#include <cuda_runtime.h>
#include <cstdint>

// Graph_Learn, 3-pass symmetric-triangle, atomic-free denominators.
// K1: tmpS on upper trapezoids -> scratch; per-tile column partials + per-row
//     partial sums (masked warp reduce). No mirror write.
// K1.5: denom[m] = rowp[m] + sum over earlier tiles of pcol[T][m]; store 1/denom.
// K2: read trapezoid once, write direct + mirror normalized output.

#define Vn 256
#define Fn 64
#define TR 4
#define NT (Vn / TR)    // 64 tiles
#define PAD 68          // floats per smem row (17 * 16B, odd quad stride)

#define SMEM_XS   (Vn * PAD)
#define SMEM_AS   (SMEM_XS)             // a[64]
#define SMEM_WS   (SMEM_AS + Fn)        // ws[8 rows][8 warps]
#define SMEM_FLOATS (SMEM_WS + 64)
#define SMEM_BYTES  (SMEM_FLOATS * 4)

typedef unsigned long long u64;

__device__ float g_tmp[32u * Vn * Vn];    // trapezoid scratch
__device__ float g_pcol[32u * NT * Vn];   // per-tile column partials
__device__ float g_rowp[32u * Vn];        // per-row partials
__device__ float g_rdn[32u * Vn];         // reciprocal denominators

__device__ __forceinline__ u64 f2add(u64 a, u64 b) {
    u64 d; asm("add.rn.f32x2 %0,%1,%2;" : "=l"(d) : "l"(a), "l"(b)); return d;
}
__device__ __forceinline__ u64 f2fma(u64 a, u64 b, u64 c) {
    u64 d; asm("fma.rn.f32x2 %0,%1,%2,%3;" : "=l"(d) : "l"(a), "l"(b), "l"(c)); return d;
}
__device__ __forceinline__ u64 f2abs(u64 a) {
    u64 d; asm("and.b64 %0,%1,0x7FFFFFFF7FFFFFFF;" : "=l"(d) : "l"(a)); return d;
}
__device__ __forceinline__ u64 packf2(float lo, float hi) {
    u64 d; asm("mov.b64 %0,{%1,%2};" : "=l"(d) : "f"(lo), "f"(hi)); return d;
}
__device__ __forceinline__ void unpackf2(u64 v, float& lo, float& hi) {
    asm("mov.b64 {%0,%1},%2;" : "=f"(lo), "=f"(hi) : "l"(v));
}
__device__ __forceinline__ void lds_2x64(uint32_t addr, u64& p0, u64& p1) {
    asm volatile("ld.shared.v2.u64 {%0,%1},[%2];" : "=l"(p0), "=l"(p1) : "r"(addr));
}

__device__ __forceinline__ void tile_rows(uint32_t xs_sh, int i0, int f0,
                                          const u64* nxj, const u64* av, u64* acc)
{
    #pragma unroll
    for (int r = 0; r < TR; ++r) {
        const uint32_t base = xs_sh + (uint32_t)(((i0 + r) * PAD + f0) * 4);
        u64 xi[8];
        lds_2x64(base +  0, xi[0], xi[1]);
        lds_2x64(base + 16, xi[2], xi[3]);
        lds_2x64(base + 32, xi[4], xi[5]);
        lds_2x64(base + 48, xi[6], xi[7]);
        u64 s = acc[r];
        #pragma unroll
        for (int k = 0; k < 8; ++k) {
            u64 d = f2abs(f2add(xi[k], nxj[k]));
            s = f2fma(d, av[k], s);
        }
        acc[r] = s;
    }
}

__device__ __forceinline__ float wred(float v) {
    v += __shfl_xor_sync(0xffffffffu, v, 16);
    v += __shfl_xor_sync(0xffffffffu, v, 8);
    v += __shfl_xor_sync(0xffffffffu, v, 4);
    v += __shfl_xor_sync(0xffffffffu, v, 2);
    v += __shfl_xor_sync(0xffffffffu, v, 1);
    return v;
}

__global__ __launch_bounds__(256, 3)
void gl_k1(const float* __restrict__ x, const float* __restrict__ a)
{
    extern __shared__ float sm[];
    float* xs  = sm;
    float* as_ = sm + SMEM_AS;
    float* ws  = sm + SMEM_WS;      // [8 rows][8 warps]

    const int tid = threadIdx.x;
    const int bt  = blockIdx.x;
    const int k   = blockIdx.y;
    const int iA  = k * TR;
    const int iB  = (Vn - TR) - k * TR;

    const float4* xp = (const float4*)(x + (size_t)bt * Vn * Fn);
    #pragma unroll
    for (int it = 0; it < 16; ++it) {
        int kk = tid + it * 256;
        float4 v = xp[kk];
        int row = kk >> 4, fc = (kk & 15) << 2;
        *(float4*)&xs[row * PAD + fc] = v;
    }
    if (tid < Fn) as_[tid] = a[tid];
    __syncthreads();

    const int wid  = tid >> 5;
    const int lane = tid & 31;
    const bool actA = ((wid + 1) << 5) > iA;     // warp-uniform
    const bool actB = ((wid + 1) << 5) > iB;

    const uint32_t xs_sh = (uint32_t)__cvta_generic_to_shared(xs);
    const uint32_t as_sh = (uint32_t)__cvta_generic_to_shared(as_);
    const int j = tid;

    u64 accA[TR] = {0,0,0,0}, accB[TR] = {0,0,0,0};

    if (actA | actB) {
        #pragma unroll 1
        for (int c = 0; c < 4; ++c) {
            const int f0 = c << 4;
            u64 nxj[8], av[8];
            {
                const uint32_t jb = xs_sh + (uint32_t)((j * PAD + f0) * 4);
                u64 t[8];
                lds_2x64(jb +  0, t[0], t[1]);
                lds_2x64(jb + 16, t[2], t[3]);
                lds_2x64(jb + 32, t[4], t[5]);
                lds_2x64(jb + 48, t[6], t[7]);
                #pragma unroll
                for (int q = 0; q < 8; ++q) {
                    float lo, hi; unpackf2(t[q], lo, hi);
                    nxj[q] = packf2(-lo, -hi);
                }
                const uint32_t ab = as_sh + (uint32_t)(f0 * 4);
                lds_2x64(ab +  0, av[0], av[1]);
                lds_2x64(ab + 16, av[2], av[3]);
                lds_2x64(ab + 32, av[4], av[5]);
                lds_2x64(ab + 48, av[6], av[7]);
            }
            if (actA) tile_rows(xs_sh, iA, f0, nxj, av, accA);
            if (actB) tile_rows(xs_sh, iB, f0, nxj, av, accB);
        }
    }

    // finalize tmpS values (0 for inactive warps so reductions are exact)
    float fA[TR], fB[TR];
    #pragma unroll
    for (int r = 0; r < TR; ++r) {
        float lo, hi;
        unpackf2(accA[r], lo, hi);
        fA[r] = actA ? __expf(fmaxf(lo + hi, 0.f)) : 0.f;
        unpackf2(accB[r], lo, hi);
        fB[r] = actB ? __expf(fmaxf(lo + hi, 0.f)) : 0.f;
    }

    // scratch + column-partial stores (owner-written, no atomics)
    if (actA) {
        float* base = g_tmp + ((size_t)bt * Vn + iA) * Vn + j;
        #pragma unroll
        for (int r = 0; r < TR; ++r) base[(size_t)r * Vn] = fA[r];
        g_pcol[((size_t)bt * NT + (iA >> 2)) * Vn + j] = fA[0] + fA[1] + fA[2] + fA[3];
    }
    if (actB) {
        float* base = g_tmp + ((size_t)bt * Vn + iB) * Vn + j;
        #pragma unroll
        for (int r = 0; r < TR; ++r) base[(size_t)r * Vn] = fB[r];
        g_pcol[((size_t)bt * NT + (iB >> 2)) * Vn + j] = fB[0] + fB[1] + fB[2] + fB[3];
    }

    // row partials: masked warp reduce, all warps participate
    #pragma unroll
    for (int r = 0; r < TR; ++r) {
        float v = (j >= iA) ? fA[r] : 0.f;      // fA already 0 if !actA
        v = wred(v);
        if (lane == 0) ws[r * 8 + wid] = v;
    }
    #pragma unroll
    for (int r = 0; r < TR; ++r) {
        float v = (j >= iB) ? fB[r] : 0.f;
        v = wred(v);
        if (lane == 0) ws[(TR + r) * 8 + wid] = v;
    }
    __syncthreads();
    if (tid < 2 * TR) {
        float s = 0.f;
        #pragma unroll
        for (int q = 0; q < 8; ++q) s += ws[tid * 8 + q];
        int m = (tid < TR) ? (iA + tid) : (iB + tid - TR);
        g_rowp[bt * Vn + m] = s;
    }
}

// K1.5: assemble denominators, store reciprocals. 32 blocks.
__global__ __launch_bounds__(256, 4)
void gl_k15()
{
    const int bt = blockIdx.x;
    const int j  = threadIdx.x;
    float s = g_rowp[bt * Vn + j];
    const float* pc = g_pcol + (size_t)bt * NT * Vn + j;
    #pragma unroll 16
    for (int T = 0; T < NT - 1; ++T) {
        float v = pc[(size_t)T * Vn];        // unconditional load (max MLP)
        if (j >= 4 * T + 4) s += v;          // predicated add: earlier tiles only
    }
    g_rdn[bt * Vn + j] = __fdividef(1.0f, s);
}

// K2: read trapezoid + reciprocals, write direct + mirror. No barriers/shfl.
__global__ __launch_bounds__(256, 8)
void gl_k2(float* __restrict__ out)
{
    const int j  = threadIdx.x;
    const int bt = blockIdx.x;
    const int k  = blockIdx.y;
    const int iA = k * TR;
    const int iB = (Vn - TR) - k * TR;

    const float* sc = g_tmp + (size_t)bt * Vn * Vn;
    float fA[TR], fB[TR];
    #pragma unroll
    for (int r = 0; r < TR; ++r) fA[r] = sc[(size_t)(iA + r) * Vn + j];
    #pragma unroll
    for (int r = 0; r < TR; ++r) fB[r] = sc[(size_t)(iB + r) * Vn + j];

    const float* rdn = g_rdn + bt * Vn;
    const float rj = rdn[j];
    float rA[TR], rB[TR];
    #pragma unroll
    for (int r = 0; r < TR; ++r) { rA[r] = rdn[iA + r]; rB[r] = rdn[iB + r]; }

    float* o = out + (size_t)bt * Vn * Vn;
    if (j >= iA) {
        #pragma unroll
        for (int r = 0; r < TR; ++r) o[(size_t)(iA + r) * Vn + j] = fA[r] * rA[r];
        *(float4*)&o[(size_t)j * Vn + iA] =
            make_float4(fA[0] * rj, fA[1] * rj, fA[2] * rj, fA[3] * rj);
    }
    if (j >= iB) {
        #pragma unroll
        for (int r = 0; r < TR; ++r) o[(size_t)(iB + r) * Vn + j] = fB[r] * rB[r];
        *(float4*)&o[(size_t)j * Vn + iB] =
            make_float4(fB[0] * rj, fB[1] * rj, fB[2] * rj, fB[3] * rj);
    }
}

extern "C" void kernel_launch(void* const* d_in, const int* in_sizes, int n_in,
                              void* d_out, int out_size)
{
    const float* x = (const float*)d_in[0];
    const float* a = (const float*)d_in[1];
    if (n_in >= 2 && in_sizes[0] == Fn && in_sizes[1] > Fn) {
        x = (const float*)d_in[1];
        a = (const float*)d_in[0];
    }
    int bt = in_sizes[0] == Fn ? in_sizes[1] / (Vn * Fn) : in_sizes[0] / (Vn * Fn);

    cudaFuncSetAttribute(gl_k1, cudaFuncAttributeMaxDynamicSharedMemorySize,
                         SMEM_BYTES);
    dim3 g1(bt, Vn / (2 * TR));
    gl_k1<<<g1, 256, SMEM_BYTES>>>(x, a);
    gl_k15<<<bt, 256>>>();
    dim3 g2(bt, Vn / (2 * TR));
    gl_k2<<<g2, 256>>>((float*)d_out);
}